// round 1
// baseline (speedup 1.0000x reference)
#include <cuda_runtime.h>
#include <math.h>

// Problem constants
#define NTOK 8192      // B*S = 4*2048
#define DIM  1024      // D
#define NE   8         // experts
#define TOPK 2
#define EPSV 1e-4f
#define WTHR 0.1f

// -------- device scratch (no allocations allowed) --------
__device__ int   g_cnt[NE];
__device__ int   g_tok[NE][NTOK];
__device__ float g_wt [NE][NTOK];

// -------- zero the per-expert counters (runs each replay) --------
__global__ void init_counts_kernel() {
    if (threadIdx.x < NE) g_cnt[threadIdx.x] = 0;
}

// -------- gating: scores -> clamp -> softmax -> top2 -> weights -> bucket --------
// One warp per token. 256 threads/block = 8 tokens/block.
__global__ __launch_bounds__(256) void gating_kernel(
    const float* __restrict__ x,      // [NTOK, DIM]
    const float* __restrict__ gW,     // [DIM, NE]
    const float* __restrict__ gb)     // [NE]
{
    const int warp = threadIdx.x >> 5;
    const int lane = threadIdx.x & 31;
    const int t = blockIdx.x * 8 + warp;
    if (t >= NTOK) return;

    const float* xr = x + (size_t)t * DIM;

    float s[NE];
#pragma unroll
    for (int e = 0; e < NE; e++) s[e] = 0.0f;

    // dot(x_row, gate_W[:, e]) for all 8 experts
    for (int d = lane; d < DIM; d += 32) {
        float xv = xr[d];
        const float* gr = gW + d * NE;
#pragma unroll
        for (int e = 0; e < NE; e++) s[e] = fmaf(xv, gr[e], s[e]);
    }
    // warp reduce each expert score
#pragma unroll
    for (int e = 0; e < NE; e++) {
#pragma unroll
        for (int off = 16; off > 0; off >>= 1)
            s[e] += __shfl_xor_sync(0xffffffffu, s[e], off);
    }

    if (lane == 0) {
        float p[NE];
        float m = -1e30f;
#pragma unroll
        for (int e = 0; e < NE; e++) {
            float sc = s[e] + gb[e];      // TEMP = 1.0
            sc = fmaxf(sc, EPSV);         // clamp-min(eps) BEFORE softmax
            p[e] = sc;
            m = fmaxf(m, sc);
        }
        float sum = 0.0f;
#pragma unroll
        for (int e = 0; e < NE; e++) { p[e] = expf(p[e] - m); sum += p[e]; }
        float inv = 1.0f / sum;
#pragma unroll
        for (int e = 0; e < NE; e++) p[e] *= inv;

        // top-2 (strict '>' keeps lowest index on ties, matching jax top_k)
        int   i0 = 0; float b0 = p[0];
#pragma unroll
        for (int e = 1; e < NE; e++) if (p[e] > b0) { b0 = p[e]; i0 = e; }
        int   i1 = (i0 == 0) ? 1 : 0; float b1 = -1.0f;
#pragma unroll
        for (int e = 0; e < NE; e++) if (e != i0 && p[e] > b1) { b1 = p[e]; i1 = e; }

        float w0 = fmaxf(b0, WTHR);
        float w1 = fmaxf(b1, WTHR);
        float invtot = 1.0f / (w0 + w1);
        // fold the final /K into the stored weight
        float c0 = w0 * invtot * (1.0f / (float)TOPK);
        float c1 = w1 * invtot * (1.0f / (float)TOPK);

        int p0 = atomicAdd(&g_cnt[i0], 1);
        g_tok[i0][p0] = t; g_wt[i0][p0] = c0;
        int p1 = atomicAdd(&g_cnt[i1], 1);
        g_tok[i1][p1] = t; g_wt[i1][p1] = c1;
    }
}

// -------- gathered per-expert GEMM, scatter via atomicAdd --------
// Tile: 64 tokens x 64 features, KT=16, 256 threads, 4x4 microtile/thread.
#define TM 64
#define TN 64
#define KT 16

__global__ __launch_bounds__(256) void expert_gemm_kernel(
    const float* __restrict__ x,      // [NTOK, DIM]
    const float* __restrict__ eW,     // [NE, DIM, DIM] (edf: out[f] += x[d]*W[e,d,f])
    const float* __restrict__ eb,     // [NE, DIM]
    float* __restrict__ out)          // [NTOK, DIM] (pre-zeroed)
{
    const int e   = blockIdx.z;
    const int cnt = g_cnt[e];
    const int m0  = blockIdx.y * TM;
    if (m0 >= cnt) return;
    const int f0  = blockIdx.x * TN;

    __shared__ float Xs[TM][KT];
    __shared__ float Ws[KT][TN];
    __shared__ int   stok[TM];
    __shared__ float swt[TM];

    const int tid = threadIdx.x;
    if (tid < TM) {
        int idx = m0 + tid;
        if (idx < cnt) { stok[tid] = g_tok[e][idx]; swt[tid] = g_wt[e][idx]; }
        else           { stok[tid] = 0;             swt[tid] = 0.0f;         }
    }
    __syncthreads();

    const int tx = tid & 15;       // feature dir, 4 cols each
    const int ty = tid >> 4;       // token dir, 4 rows each

    // A-load mapping: thread loads token row (tid/4), k cols ((tid%4)*4 .. +3)
    const int am = tid >> 2;
    const int ak = (tid & 3) << 2;
    const float* xrow = x + (size_t)stok[am] * DIM + ak;

    // W-load mapping: thread loads k row (tid/16), f cols ((tid%16)*4 .. +3)
    const int wk = tid >> 4;
    const int wf = (tid & 15) << 2;
    const float* We = eW + (size_t)e * DIM * DIM + f0;

    float acc[4][4];
#pragma unroll
    for (int i = 0; i < 4; i++)
#pragma unroll
        for (int j = 0; j < 4; j++) acc[i][j] = 0.0f;

    for (int k0 = 0; k0 < DIM; k0 += KT) {
        float4 av = *(const float4*)(xrow + k0);
        float4 wv = *(const float4*)(We + (size_t)(k0 + wk) * DIM + wf);
        __syncthreads();   // previous tile fully consumed
        *(float4*)&Xs[am][ak] = av;
        *(float4*)&Ws[wk][wf] = wv;
        __syncthreads();   // tile ready

#pragma unroll
        for (int kk = 0; kk < KT; kk++) {
            float a0 = Xs[ty * 4 + 0][kk];
            float a1 = Xs[ty * 4 + 1][kk];
            float a2 = Xs[ty * 4 + 2][kk];
            float a3 = Xs[ty * 4 + 3][kk];
            float4 b = *(const float4*)&Ws[kk][tx * 4];
            acc[0][0] = fmaf(a0, b.x, acc[0][0]);
            acc[0][1] = fmaf(a0, b.y, acc[0][1]);
            acc[0][2] = fmaf(a0, b.z, acc[0][2]);
            acc[0][3] = fmaf(a0, b.w, acc[0][3]);
            acc[1][0] = fmaf(a1, b.x, acc[1][0]);
            acc[1][1] = fmaf(a1, b.y, acc[1][1]);
            acc[1][2] = fmaf(a1, b.z, acc[1][2]);
            acc[1][3] = fmaf(a1, b.w, acc[1][3]);
            acc[2][0] = fmaf(a2, b.x, acc[2][0]);
            acc[2][1] = fmaf(a2, b.y, acc[2][1]);
            acc[2][2] = fmaf(a2, b.z, acc[2][2]);
            acc[2][3] = fmaf(a2, b.w, acc[2][3]);
            acc[3][0] = fmaf(a3, b.x, acc[3][0]);
            acc[3][1] = fmaf(a3, b.y, acc[3][1]);
            acc[3][2] = fmaf(a3, b.z, acc[3][2]);
            acc[3][3] = fmaf(a3, b.w, acc[3][3]);
        }
    }

    // epilogue: out[tok, f] += w * (acc + bias). Exactly 2 atomic addends per
    // output element across the whole grid (K=2), addition commutative ->
    // deterministic.
    const float* brow = eb + (size_t)e * DIM + f0 + tx * 4;
#pragma unroll
    for (int i = 0; i < 4; i++) {
        int row = ty * 4 + i;
        if (m0 + row < cnt) {
            float w = swt[row];
            float* orow = out + (size_t)stok[row] * DIM + f0 + tx * 4;
#pragma unroll
            for (int j = 0; j < 4; j++)
                atomicAdd(orow + j, w * (acc[i][j] + brow[j]));
        }
    }
}

extern "C" void kernel_launch(void* const* d_in, const int* in_sizes, int n_in,
                              void* d_out, int out_size)
{
    const float* x  = (const float*)d_in[0];   // [4,2048,1024]
    const float* gW = (const float*)d_in[1];   // [1024,8]
    const float* gb = (const float*)d_in[2];   // [8]
    const float* eW = (const float*)d_in[3];   // [8,1024,1024]
    const float* eb = (const float*)d_in[4];   // [8,1024]
    float* out = (float*)d_out;                // [4,2048,1024]

    (void)in_sizes; (void)n_in;

    // output is poisoned; we accumulate into it -> zero first
    cudaMemsetAsync(d_out, 0, (size_t)out_size * sizeof(float));

    init_counts_kernel<<<1, 32>>>();
    gating_kernel<<<NTOK / 8, 256>>>(x, gW, gb);

    dim3 grid(DIM / TN, NTOK / TM, NE);   // 16 x 128 x 8; tiles past count exit early
    expert_gemm_kernel<<<grid, 256>>>(x, eW, eb, out);
    (void)out;
}

// round 4
// speedup vs baseline: 2.3629x; 2.3629x over previous
#include <cuda_runtime.h>
#include <cuda_bf16.h>
#include <cstdint>
#include <math.h>

// Problem constants
#define NTOK 8192      // B*S
#define DIM  1024
#define NE   8
#define EPSV 1e-4f
#define WTHR 0.1f

// GEMM tile
#define BM 128
#define BN 128
#define BK 32
#define NKCH (DIM / BK)   // 32

// smem byte offsets (dynamic)
#define SM_TOK   0                    // 128 * 4  (packed (tok<<1)|slot)
#define SM_WT    512                  // 128 * 4
#define SM_BIAS  1024                 // 128 * 4
#define SM_A_HI  1536                 // 128 rows * 80B (stride 40 bf16)
#define SM_A_LO  (SM_A_HI + 10240)
#define SM_B_HI  (SM_A_LO + 10240)   // 32 rows * 272B (stride 136 bf16)
#define SM_B_LO  (SM_B_HI + 8704)
#define SM_TOTAL (SM_B_LO + 8704)    // 39424 B < 48KB -> no attribute needed

#define ASTRIDE 80                    // bytes per A smem row
#define BSTRIDE 272                   // bytes per B smem row

// -------- device scratch (module-static; no runtime allocation) --------
__device__ int   g_cnt[NE];
__device__ int   g_tok[NE][NTOK];     // (token<<1) | slot
__device__ float g_wt [NE][NTOK];
__device__ float g_part[2ull * NTOK * DIM];   // 64MB scratch, fully rewritten each run

// -------- helpers --------
__device__ __forceinline__ uint32_t smem_u32(const void* p) {
    uint32_t a;
    asm("{ .reg .u64 t; cvta.to.shared.u64 t, %1; cvt.u32.u64 %0, t; }" : "=r"(a) : "l"(p));
    return a;
}
__device__ __forceinline__ void ldsm_x4(uint32_t* r, uint32_t addr) {
    asm volatile("ldmatrix.sync.aligned.m8n8.x4.shared.b16 {%0,%1,%2,%3}, [%4];"
                 : "=r"(r[0]), "=r"(r[1]), "=r"(r[2]), "=r"(r[3]) : "r"(addr));
}
__device__ __forceinline__ void ldsm_x4_t(uint32_t* r, uint32_t addr) {
    asm volatile("ldmatrix.sync.aligned.m8n8.x4.trans.shared.b16 {%0,%1,%2,%3}, [%4];"
                 : "=r"(r[0]), "=r"(r[1]), "=r"(r[2]), "=r"(r[3]) : "r"(addr));
}
__device__ __forceinline__ void mma_bf16(float* d, const uint32_t* a, uint32_t b0, uint32_t b1) {
    asm volatile(
        "mma.sync.aligned.m16n8k16.row.col.f32.bf16.bf16.f32 "
        "{%0,%1,%2,%3}, {%4,%5,%6,%7}, {%8,%9}, {%0,%1,%2,%3};"
        : "+f"(d[0]), "+f"(d[1]), "+f"(d[2]), "+f"(d[3])
        : "r"(a[0]), "r"(a[1]), "r"(a[2]), "r"(a[3]), "r"(b0), "r"(b1));
}
// pack two floats' bf16-hi into one u32; compute lo residuals
__device__ __forceinline__ void split2(float x, float y, uint32_t& hi, uint32_t& lo) {
    __nv_bfloat16 hx = __float2bfloat16_rn(x);
    __nv_bfloat16 hy = __float2bfloat16_rn(y);
    float rx = x - __bfloat162float(hx);
    float ry = y - __bfloat162float(hy);
    __nv_bfloat162 h = __nv_bfloat162(hx, hy);
    __nv_bfloat162 l = __nv_bfloat162(__float2bfloat16_rn(rx), __float2bfloat16_rn(ry));
    hi = *reinterpret_cast<uint32_t*>(&h);
    lo = *reinterpret_cast<uint32_t*>(&l);
}

// ================= kernels =================

__global__ void init_counts_kernel() {
    if (threadIdx.x < NE) g_cnt[threadIdx.x] = 0;
}

// gating: one warp per token; records (token, slot, weight) per expert
__global__ __launch_bounds__(256) void gating_kernel(
    const float* __restrict__ x, const float* __restrict__ gW, const float* __restrict__ gb)
{
    const int warp = threadIdx.x >> 5;
    const int lane = threadIdx.x & 31;
    const int t = blockIdx.x * 8 + warp;
    if (t >= NTOK) return;
    const float* xr = x + (size_t)t * DIM;

    float s[NE];
#pragma unroll
    for (int e = 0; e < NE; e++) s[e] = 0.0f;
    for (int d = lane; d < DIM; d += 32) {
        float xv = xr[d];
        const float* gr = gW + d * NE;
#pragma unroll
        for (int e = 0; e < NE; e++) s[e] = fmaf(xv, gr[e], s[e]);
    }
#pragma unroll
    for (int e = 0; e < NE; e++) {
#pragma unroll
        for (int off = 16; off > 0; off >>= 1)
            s[e] += __shfl_xor_sync(0xffffffffu, s[e], off);
    }
    if (lane == 0) {
        float p[NE];
        float m = -1e30f;
#pragma unroll
        for (int e = 0; e < NE; e++) {
            float sc = fmaxf(s[e] + gb[e], EPSV);
            p[e] = sc; m = fmaxf(m, sc);
        }
        float sum = 0.0f;
#pragma unroll
        for (int e = 0; e < NE; e++) { p[e] = expf(p[e] - m); sum += p[e]; }
        float inv = 1.0f / sum;
#pragma unroll
        for (int e = 0; e < NE; e++) p[e] *= inv;

        int i0 = 0; float b0 = p[0];
#pragma unroll
        for (int e = 1; e < NE; e++) if (p[e] > b0) { b0 = p[e]; i0 = e; }
        int i1 = (i0 == 0) ? 1 : 0; float b1 = -1.0f;
#pragma unroll
        for (int e = 0; e < NE; e++) if (e != i0 && p[e] > b1) { b1 = p[e]; i1 = e; }

        float w0 = fmaxf(b0, WTHR);
        float w1 = fmaxf(b1, WTHR);
        float invtot = 1.0f / (w0 + w1);
        float c0 = w0 * invtot * 0.5f;    // fold /K
        float c1 = w1 * invtot * 0.5f;

        int p0 = atomicAdd(&g_cnt[i0], 1);
        g_tok[i0][p0] = (t << 1) | 0; g_wt[i0][p0] = c0;
        int p1 = atomicAdd(&g_cnt[i1], 1);
        g_tok[i1][p1] = (t << 1) | 1; g_wt[i1][p1] = c1;
    }
}

// -------- bf16x3 mma.sync expert GEMM --------
__global__ __launch_bounds__(256) void moe_gemm_kernel(
    const float* __restrict__ x,      // [NTOK, DIM] fp32
    const float* __restrict__ eW,     // [NE, DIM, DIM] fp32 (d-major rows, f contiguous)
    const float* __restrict__ eb)     // [NE, DIM]
{
    extern __shared__ char smem[];
    const int e   = blockIdx.z;
    const int cnt = g_cnt[e];
    const int m0  = blockIdx.y * BM;
    if (m0 >= cnt) return;
    const int f0  = blockIdx.x * BN;

    const uint32_t sb = smem_u32(smem);
    const int tid  = threadIdx.x;
    const int lane = tid & 31;
    const int wid  = tid >> 5;
    const int wm   = wid & 1;     // 2 warp rows (64 m each)
    const int wn   = wid >> 1;    // 4 warp cols (32 n each)

    int*   stok  = (int*)(smem + SM_TOK);
    float* swt   = (float*)(smem + SM_WT);
    float* sbias = (float*)(smem + SM_BIAS);
    if (tid < BM) {
        int idx = m0 + tid;
        stok[tid] = (idx < cnt) ? g_tok[e][idx] : 0;
        swt[tid]  = (idx < cnt) ? g_wt[e][idx]  : 0.0f;
        sbias[tid] = eb[(size_t)e * DIM + f0 + tid];
    }
    __syncthreads();

    // ---- prefetch chunk 0 into registers ----
    // A: 128 rows x 32 k (8 float4 cols). 1024 float4 / 256 thr = 4 each.
    // B: 32 k-rows x 128 f (32 float4 cols). 4 each.
    float4 pa[4], pb[4];
    const int arow[4] = { (tid + 0) >> 3, (tid + 256) >> 3, (tid + 512) >> 3, (tid + 768) >> 3 };
    const int ac4 = tid & 7;
    const int brow = tid >> 5;           // base k-row; +8 per j
    const int bc4  = tid & 31;
    const float* Wbase = eW + (size_t)e * DIM * DIM + f0;

#pragma unroll
    for (int j = 0; j < 4; j++)
        pa[j] = *(const float4*)(x + (size_t)(stok[arow[j]] >> 1) * DIM + 0 + ac4 * 4);
#pragma unroll
    for (int j = 0; j < 4; j++)
        pb[j] = *(const float4*)(Wbase + (size_t)(0 + brow + j * 8) * DIM + bc4 * 4);

    float acc[4][4][4];
#pragma unroll
    for (int i = 0; i < 4; i++)
#pragma unroll
        for (int jj = 0; jj < 4; jj++)
#pragma unroll
            for (int r = 0; r < 4; r++) acc[i][jj][r] = 0.0f;

    // precomputed ldmatrix base offsets
    const uint32_t a_off = (uint32_t)((wm * 64 + (lane & 15)) * ASTRIDE + ((lane >> 4) & 1) * 16);
    const uint32_t b_off = (uint32_t)((lane & 15) * BSTRIDE + wn * 64 + ((lane >> 4) & 1) * 16);

    for (int c = 0; c < NKCH; c++) {
        __syncthreads();   // smem consumers of previous chunk done

        // store prefetched chunk (convert fp32 -> bf16 hi/lo)
#pragma unroll
        for (int j = 0; j < 4; j++) {
            uint32_t h01, l01, h23, l23;
            split2(pa[j].x, pa[j].y, h01, l01);
            split2(pa[j].z, pa[j].w, h23, l23);
            uint32_t off = (uint32_t)(arow[j] * ASTRIDE + ac4 * 8);
            *(uint2*)(smem + SM_A_HI + off) = make_uint2(h01, h23);
            *(uint2*)(smem + SM_A_LO + off) = make_uint2(l01, l23);
        }
#pragma unroll
        for (int j = 0; j < 4; j++) {
            uint32_t h01, l01, h23, l23;
            split2(pb[j].x, pb[j].y, h01, l01);
            split2(pb[j].z, pb[j].w, h23, l23);
            uint32_t off = (uint32_t)((brow + j * 8) * BSTRIDE + bc4 * 8);
            *(uint2*)(smem + SM_B_HI + off) = make_uint2(h01, h23);
            *(uint2*)(smem + SM_B_LO + off) = make_uint2(l01, l23);
        }
        __syncthreads();

        // prefetch next chunk (LDGs overlap the MMA work below)
        if (c + 1 < NKCH) {
            const int k0 = (c + 1) * BK;
#pragma unroll
            for (int j = 0; j < 4; j++)
                pa[j] = *(const float4*)(x + (size_t)(stok[arow[j]] >> 1) * DIM + k0 + ac4 * 4);
#pragma unroll
            for (int j = 0; j < 4; j++)
                pb[j] = *(const float4*)(Wbase + (size_t)(k0 + brow + j * 8) * DIM + bc4 * 4);
        }

        // compute current chunk: 2 k-steps of m16n8k16
#pragma unroll
        for (int ks = 0; ks < 2; ks++) {
            uint32_t ah[4][4], al[4][4];
#pragma unroll
            for (int mt = 0; mt < 4; mt++) {
                uint32_t ad = sb + SM_A_HI + a_off + (uint32_t)(mt * 16 * ASTRIDE + ks * 32);
                ldsm_x4(ah[mt], ad);
                ldsm_x4(al[mt], ad + (SM_A_LO - SM_A_HI));
            }
#pragma unroll
            for (int nb2 = 0; nb2 < 2; nb2++) {
                uint32_t bh[4], bl[4];
                uint32_t bd = sb + SM_B_HI + b_off + (uint32_t)(ks * 16 * BSTRIDE + nb2 * 32);
                ldsm_x4_t(bh, bd);
                ldsm_x4_t(bl, bd + (SM_B_LO - SM_B_HI));
#pragma unroll
                for (int mt = 0; mt < 4; mt++) {
                    mma_bf16(acc[mt][nb2 * 2 + 0], ah[mt], bh[0], bh[1]);
                    mma_bf16(acc[mt][nb2 * 2 + 0], ah[mt], bl[0], bl[1]);
                    mma_bf16(acc[mt][nb2 * 2 + 0], al[mt], bh[0], bh[1]);
                    mma_bf16(acc[mt][nb2 * 2 + 1], ah[mt], bh[2], bh[3]);
                    mma_bf16(acc[mt][nb2 * 2 + 1], ah[mt], bl[2], bl[3]);
                    mma_bf16(acc[mt][nb2 * 2 + 1], al[mt], bh[2], bh[3]);
                }
            }
        }
    }

    // ---- epilogue: write-once into g_part[slot][tok][f] ----
#pragma unroll
    for (int mt = 0; mt < 4; mt++) {
#pragma unroll
        for (int half = 0; half < 2; half++) {
            int m = wm * 64 + mt * 16 + (lane >> 2) + half * 8;
            if (m0 + m < cnt) {
                int te = stok[m];
                float w = swt[m];
                float* dst = g_part + ((size_t)(te & 1) * NTOK + (size_t)(te >> 1)) * DIM
                           + f0 + wn * 32;
#pragma unroll
                for (int nidx = 0; nidx < 4; nidx++) {
                    int cb = nidx * 8 + (lane & 3) * 2;
                    float v0 = w * (acc[mt][nidx][half * 2 + 0] + sbias[wn * 32 + cb]);
                    float v1 = w * (acc[mt][nidx][half * 2 + 1] + sbias[wn * 32 + cb + 1]);
                    *(float2*)(dst + cb) = make_float2(v0, v1);
                }
            }
        }
    }
}

// out = part0 + part1 (covers every element; no memset needed)
__global__ __launch_bounds__(256) void combine_kernel(float* __restrict__ out) {
    size_t i = ((size_t)blockIdx.x * 256 + threadIdx.x) * 4;
    const float4 a = *(const float4*)(g_part + i);
    const float4 b = *(const float4*)(g_part + (size_t)NTOK * DIM + i);
    *(float4*)(out + i) = make_float4(a.x + b.x, a.y + b.y, a.z + b.z, a.w + b.w);
}

// ================= host =================
extern "C" void kernel_launch(void* const* d_in, const int* in_sizes, int n_in,
                              void* d_out, int out_size)
{
    const float* x  = (const float*)d_in[0];   // [4,2048,1024]
    const float* gW = (const float*)d_in[1];   // [1024,8]
    const float* gb = (const float*)d_in[2];   // [8]
    const float* eW = (const float*)d_in[3];   // [8,1024,1024]
    const float* eb = (const float*)d_in[4];   // [8,1024]
    float* out = (float*)d_out;
    (void)in_sizes; (void)n_in; (void)out_size;

    init_counts_kernel<<<1, 32>>>();
    gating_kernel<<<NTOK / 8, 256>>>(x, gW, gb);

    dim3 grid(DIM / BN, NTOK / BM, NE);   // (8, 64, 8); tiles past count exit early
    moe_gemm_kernel<<<grid, 256, SM_TOTAL>>>(x, eW, eb);

    combine_kernel<<<(NTOK * DIM / 4) / 256, 256>>>(out);
}